// round 9
// baseline (speedup 1.0000x reference)
#include <cuda_runtime.h>
#include <cuda_bf16.h>
#include <cstdint>
#include <math.h>

// ---------------- problem constants ----------------
#define B_SZ     256
#define N_TOK    197
#define D_L      512
#define D_G      768
#define M_FINE   (B_SZ * N_TOK)          // 50432
#define TOPK     5

#define OFF_G    0
#define OFF_LS   (B_SZ * D_G)                         // 196608
#define OFF_FINE (OFF_LS + 1)                         // 196609
#define OFF_TOP  (OFF_FINE + (size_t)M_FINE * D_L)

// ---------------- device scratch (weights pre-split; activations stay fp32) ----------------
__device__ __align__(16) __nv_bfloat16 g_W1h[D_L * D_L], g_W1l[D_L * D_L];
__device__ __align__(16) __nv_bfloat16 g_W2h[D_L * D_L], g_W2l[D_L * D_L];
__device__ __align__(16) __nv_bfloat16 g_V1h[D_G * D_L], g_V1l[D_G * D_L];
__device__ __align__(16) __nv_bfloat16 g_V2h[D_G * D_G], g_V2l[D_G * D_G];
__device__ __align__(16) float g_Hf[(size_t)M_FINE * D_L];
__device__ __align__(16) float g_Hg[B_SZ * D_G];
__device__ __align__(16) float g_G [B_SZ * D_G];
__device__ __align__(16) float g_sums_f[2 * D_L];
__device__ __align__(16) float g_sums_g[2 * D_G];
__device__ __align__(16) float g_scale_f[D_L], g_shift_f[D_L];
__device__ __align__(16) float g_scale_g[D_G], g_shift_g[D_G];

// ---------------- helpers ----------------
__device__ __forceinline__ uint32_t s2u(const void* p) {
    uint32_t a;
    asm("{ .reg .u64 t; cvta.to.shared.u64 t, %1; cvt.u32.u64 %0, t; }" : "=r"(a) : "l"(p));
    return a;
}
__device__ __forceinline__ void ldsm_x4(uint32_t* r, uint32_t addr) {
    asm volatile("ldmatrix.sync.aligned.m8n8.x4.shared.b16 {%0,%1,%2,%3}, [%4];"
        : "=r"(r[0]), "=r"(r[1]), "=r"(r[2]), "=r"(r[3]) : "r"(addr));
}
__device__ __forceinline__ void mma16816(float* c, const uint32_t* a, const uint32_t* b) {
    asm volatile("mma.sync.aligned.m16n8k16.row.col.f32.bf16.bf16.f32 "
        "{%0,%1,%2,%3}, {%4,%5,%6,%7}, {%8,%9}, {%0,%1,%2,%3};"
        : "+f"(c[0]), "+f"(c[1]), "+f"(c[2]), "+f"(c[3])
        : "r"(a[0]), "r"(a[1]), "r"(a[2]), "r"(a[3]), "r"(b[0]), "r"(b[1]));
}
__device__ __forceinline__ void split1(float v, __nv_bfloat16& h, __nv_bfloat16& l) {
    h = __float2bfloat16(v);
    l = __float2bfloat16(v - __bfloat162float(h));
}

// ---------------- HMMA GEMM: C[M,N] = op(A)[M,K] @ W[N,K]^T + bias ----------------
// A fp32 in global; split to bf16 hi/lo in-register during tile load.
// op(A) = relu(A*bnscale + bnshift) per K-channel if BNRELU.
// W pre-split bf16 hi/lo. 3-term product: ahi*bhi + ahi*blo + alo*bhi.
// CTA tile 128x128, BK=32, 8 warps (warp tile 32x64), double-buffered smem.
//
// per-stage smem layout (bytes): AH 0 | AL 10240 | BH 20480 | BL 30720 ; stage stride 40960
// tile rows padded to 40 halves (80 B) -> ldmatrix phase-conflict-free.
template<bool BNRELU>
__global__ void __launch_bounds__(256, 2)
mma_gemm_kernel(const float* __restrict__ A,
                const __nv_bfloat16* __restrict__ Wh, const __nv_bfloat16* __restrict__ Wl,
                const float* __restrict__ bias,
                const float* __restrict__ bnscale, const float* __restrict__ bnshift,
                float* __restrict__ C, int N, int K)
{
    extern __shared__ char sm[];
    const uint32_t sbase = s2u(sm);
    const int tid  = threadIdx.x;
    const int lane = tid & 31, wid = tid >> 5;
    const int wm = wid & 3, wn = wid >> 2;          // 4 x 2 warp grid
    const int m0 = blockIdx.y * 128, n0 = blockIdx.x * 128;

    const int grp = lane >> 3, gr = lane & 7;

    // ldmatrix addresses (stage 0; add stage*40960 / mt*1280 / nt*640 / k16*32)
    const uint32_t aHiAddr = sbase + (uint32_t)((wm * 32 + gr + (grp & 1) * 8) * 80 + (grp >> 1) * 16);
    const uint32_t aLoAddr = aHiAddr + 10240u;
    const uint32_t bAddr   = sbase + (grp < 2 ? 20480u : 30720u)
                           + (uint32_t)((wn * 64 + gr) * 80 + (grp & 1) * 16);

    // A global->smem mapping: thread -> (row, 16-float segment)
    const int arow = tid >> 1;
    const int akk  = (tid & 1) * 16;
    const uint32_t aStsOff = (uint32_t)(arow * 80 + (tid & 1) * 32);  // bytes within AH

    float acc[2][8][4];
    #pragma unroll
    for (int i = 0; i < 2; i++)
        #pragma unroll
        for (int j = 0; j < 8; j++)
            #pragma unroll
            for (int q = 0; q < 4; q++) acc[i][j][q] = 0.0f;

    const int NT = K >> 5;
    float4 pa[4];

    auto ldgA = [&](int kc) {
        const float4* src = (const float4*)(A + (size_t)(m0 + arow) * K + kc + akk);
        #pragma unroll
        for (int i = 0; i < 4; i++) pa[i] = src[i];
    };
    auto cpB = [&](int kc, int stage) {
        const uint32_t so = (uint32_t)stage * 40960u;
        #pragma unroll
        for (int p = 0; p < 2; p++) {
            int i = tid + 256 * p; int row = i >> 2, sg = i & 3;
            uint32_t dh = sbase + so + 20480u + (uint32_t)(row * 80 + sg * 16);
            uint32_t dl = dh + 10240u;
            const __nv_bfloat16* sh = Wh + (size_t)(n0 + row) * K + kc + sg * 8;
            const __nv_bfloat16* sl = Wl + (size_t)(n0 + row) * K + kc + sg * 8;
            asm volatile("cp.async.cg.shared.global [%0], [%1], 16;" :: "r"(dh), "l"(sh));
            asm volatile("cp.async.cg.shared.global [%0], [%1], 16;" :: "r"(dl), "l"(sl));
        }
        asm volatile("cp.async.commit_group;" ::: "memory");
    };

    // prologue
    ldgA(0);
    cpB(0, 0);

    for (int kt = 0; kt < NT; kt++) {
        const int stage = kt & 1;
        const uint32_t so = (uint32_t)stage * 40960u;
        const int kc = kt << 5;

        __syncthreads();   // stage smem free (consumer 2 iters back done)

        // ---- BN + hi/lo split + STS A(kt) ----
        {
            __nv_bfloat162 hp[8], lp[8];
            #pragma unroll
            for (int i = 0; i < 4; i++) {
                float4 v = pa[i];
                if (BNRELU) {
                    float4 s = ((const float4*)(bnscale + kc + akk))[i];
                    float4 t = ((const float4*)(bnshift + kc + akk))[i];
                    v.x = fmaxf(fmaf(v.x, s.x, t.x), 0.0f);
                    v.y = fmaxf(fmaf(v.y, s.y, t.y), 0.0f);
                    v.z = fmaxf(fmaf(v.z, s.z, t.z), 0.0f);
                    v.w = fmaxf(fmaf(v.w, s.w, t.w), 0.0f);
                }
                __nv_bfloat16 h0, h1, h2, h3, l0, l1, l2, l3;
                split1(v.x, h0, l0); split1(v.y, h1, l1);
                split1(v.z, h2, l2); split1(v.w, h3, l3);
                hp[2 * i]     = __halves2bfloat162(h0, h1);
                hp[2 * i + 1] = __halves2bfloat162(h2, h3);
                lp[2 * i]     = __halves2bfloat162(l0, l1);
                lp[2 * i + 1] = __halves2bfloat162(l2, l3);
            }
            char* dsth = sm + so + aStsOff;
            char* dstl = dsth + 10240;
            ((uint4*)dsth)[0] = ((uint4*)hp)[0];
            ((uint4*)dsth)[1] = ((uint4*)hp)[1];
            ((uint4*)dstl)[0] = ((uint4*)lp)[0];
            ((uint4*)dstl)[1] = ((uint4*)lp)[1];
        }

        // ---- prefetch next stage ----
        if (kt + 1 < NT) {
            ldgA(kc + 32);
            cpB(kc + 32, stage ^ 1);
            asm volatile("cp.async.wait_group 1;" ::: "memory");
        } else {
            asm volatile("cp.async.wait_group 0;" ::: "memory");
        }
        __syncthreads();

        // ---- compute stage ----
        #pragma unroll
        for (int k16 = 0; k16 < 2; k16++) {
            const uint32_t kb = so + (uint32_t)(k16 * 32);
            uint32_t aHi[2][4], aLo[2][4];
            #pragma unroll
            for (int mt = 0; mt < 2; mt++) {
                ldsm_x4(aHi[mt], aHiAddr + kb + (uint32_t)(mt * 1280));
                ldsm_x4(aLo[mt], aLoAddr + kb + (uint32_t)(mt * 1280));
            }
            #pragma unroll
            for (int nt = 0; nt < 8; nt++) {
                uint32_t bb[4];   // bb[0..1]=Bhi frag, bb[2..3]=Blo frag
                ldsm_x4(bb, bAddr + kb + (uint32_t)(nt * 640));
                mma16816(acc[0][nt], aHi[0], bb + 0);
                mma16816(acc[1][nt], aHi[1], bb + 0);
                mma16816(acc[0][nt], aHi[0], bb + 2);
                mma16816(acc[1][nt], aHi[1], bb + 2);
                mma16816(acc[0][nt], aLo[0], bb + 0);
                mma16816(acc[1][nt], aLo[1], bb + 0);
            }
        }
    }

    // ---- epilogue: +bias, scalar stores (C may be odd-float aligned) ----
    const int erow = m0 + wm * 32 + (lane >> 2);
    const int ecol = n0 + wn * 64 + ((lane & 3) << 1);
    #pragma unroll
    for (int nt = 0; nt < 8; nt++) {
        int c = ecol + nt * 8;
        float b0 = __ldg(&bias[c]), b1 = __ldg(&bias[c + 1]);
        #pragma unroll
        for (int mt = 0; mt < 2; mt++) {
            int r = erow + mt * 16;
            C[(size_t)r * N + c]           = acc[mt][nt][0] + b0;
            C[(size_t)r * N + c + 1]       = acc[mt][nt][1] + b1;
            C[(size_t)(r + 8) * N + c]     = acc[mt][nt][2] + b0;
            C[(size_t)(r + 8) * N + c + 1] = acc[mt][nt][3] + b1;
        }
    }
}

#define GEMM_SMEM 81920

// ---------------- weight split fp32 -> bf16 hi/lo ----------------
__global__ void split_kernel(const float* __restrict__ x,
                             __nv_bfloat16* __restrict__ hi,
                             __nv_bfloat16* __restrict__ lo, int n4) {
    int i = blockIdx.x * blockDim.x + threadIdx.x;
    if (i >= n4) return;
    float4 v = ((const float4*)x)[i];
    __nv_bfloat16 h0, h1, h2, h3, l0, l1, l2, l3;
    split1(v.x, h0, l0); split1(v.y, h1, l1); split1(v.z, h2, l2); split1(v.w, h3, l3);
    ((__nv_bfloat162*)hi)[2 * (size_t)i]     = __halves2bfloat162(h0, h1);
    ((__nv_bfloat162*)hi)[2 * (size_t)i + 1] = __halves2bfloat162(h2, h3);
    ((__nv_bfloat162*)lo)[2 * (size_t)i]     = __halves2bfloat162(l0, l1);
    ((__nv_bfloat162*)lo)[2 * (size_t)i + 1] = __halves2bfloat162(l2, l3);
}

// ---------------- init: zero BN accumulators ----------------
__global__ void init_kernel() {
    int t = blockIdx.x * blockDim.x + threadIdx.x;
    if (t < 2 * D_L) g_sums_f[t] = 0.0f;
    if (t < 2 * D_G) g_sums_g[t] = 0.0f;
}

// ---------------- BN stats ----------------
template<int C, int RPB>
__global__ void stats_kernel(const float* __restrict__ H, int M, float* __restrict__ sums) {
    const int c  = threadIdx.x;
    const int r0 = blockIdx.x * RPB;
    float s = 0.0f, ss = 0.0f;
    int rend = r0 + RPB; if (rend > M) rend = M;
    for (int r = r0; r < rend; r++) {
        float v = H[(size_t)r * C + c];
        s += v;
        ss = fmaf(v, v, ss);
    }
    atomicAdd(&sums[c], s);
    atomicAdd(&sums[C + c], ss);
}

template<int C>
__global__ void bn_finalize_kernel(const float* __restrict__ sums,
                                   const float* __restrict__ gamma,
                                   const float* __restrict__ beta,
                                   float invM,
                                   float* __restrict__ scale,
                                   float* __restrict__ shift) {
    int c = threadIdx.x;
    if (c >= C) return;
    float m   = sums[c] * invM;
    float var = sums[C + c] * invM - m * m;
    float inv = rsqrtf(var + 1e-5f);
    float sc  = gamma[c] * inv;
    scale[c] = sc;
    shift[c] = beta[c] - m * sc;
}

// ---------------- L2 normalize + logit_scale ----------------
__global__ void l2norm_kernel(const float* __restrict__ G,
                              const float* __restrict__ ls,
                              float* __restrict__ out) {
    __shared__ float red[256];
    const int r = blockIdx.x, t = threadIdx.x;
    const float* g = G + (size_t)r * D_G;
    float s = 0.0f;
    for (int c = t; c < D_G; c += 256) { float v = g[c]; s = fmaf(v, v, s); }
    red[t] = s; __syncthreads();
    for (int o = 128; o > 0; o >>= 1) {
        if (t < o) red[t] += red[t + o];
        __syncthreads();
    }
    float inv = rsqrtf(red[0]);
    for (int c = t; c < D_G; c += 256)
        out[OFF_G + (size_t)r * D_G + c] = g[c] * inv;
    if (r == 0 && t == 0) out[OFF_LS] = expf(ls[0]);
}

// ---------------- token mean -> top row 6 ----------------
__global__ void token_mean_kernel(const float* __restrict__ X2, float* __restrict__ outTop) {
    const int b = blockIdx.x, d = threadIdx.x;   // blockDim = 512
    const float* p = X2 + (size_t)b * N_TOK * D_L + d;
    float s = 0.0f;
    #pragma unroll 4
    for (int n = 0; n < N_TOK; n++) s += p[(size_t)n * D_L];
    outTop[((size_t)b * (TOPK + 2) + (TOPK + 1)) * D_L + d] = s * (1.0f / (float)N_TOK);
}

// ---------------- top-k gather ----------------
__global__ void topk_gather_kernel(const float* __restrict__ attn,
                                   const float* __restrict__ X2,
                                   float* __restrict__ outTop) {
    __shared__ float sv[256];
    __shared__ int   si[256];
    __shared__ int   sel[TOPK + 1];
    const int b = blockIdx.x, t = threadIdx.x;
    const float NEG = __int_as_float(0xff800000);

    float myv = (t < N_TOK - 1) ? attn[(size_t)b * (N_TOK - 1) + t] : NEG;
    if (t == 0) sel[0] = 0;
    __syncthreads();

    for (int k = 0; k < TOPK; k++) {
        sv[t] = myv; si[t] = t;
        __syncthreads();
        for (int o = 128; o > 0; o >>= 1) {
            if (t < o) {
                float v2 = sv[t + o]; int i2 = si[t + o];
                if (v2 > sv[t] || (v2 == sv[t] && i2 < si[t])) { sv[t] = v2; si[t] = i2; }
            }
            __syncthreads();
        }
        int win = si[0];
        if (t == 0)  sel[k + 1] = win + 1;
        if (t == win) myv = NEG;
        __syncthreads();
    }

    #pragma unroll
    for (int j = 0; j < TOPK + 1; j++) {
        int row = sel[j];
        const float* src = X2 + ((size_t)b * N_TOK + row) * D_L;
        float* dst = outTop + ((size_t)b * (TOPK + 2) + j) * D_L;
        for (int d = t; d < D_L; d += 256) dst[d] = src[d];
    }
}

// ---------------- launch ----------------
extern "C" void kernel_launch(void* const* d_in, const int* in_sizes, int n_in,
                              void* d_out, int out_size)
{
    const float* image_features = (const float*)d_in[0];
    const float* fine_feat      = (const float*)d_in[1];
    const float* fine_attn      = (const float*)d_in[2];
    const float* logit_scale    = (const float*)d_in[3];
    const float* vpt_w1  = (const float*)d_in[4];
    const float* vpt_b1  = (const float*)d_in[5];
    const float* vpt_g1  = (const float*)d_in[6];
    const float* vpt_be1 = (const float*)d_in[7];
    const float* vpt_w2  = (const float*)d_in[8];
    const float* vpt_b2  = (const float*)d_in[9];
    const float* mid_w1  = (const float*)d_in[10];
    const float* mid_b1  = (const float*)d_in[11];
    const float* mid_g1  = (const float*)d_in[12];
    const float* mid_be1 = (const float*)d_in[13];
    const float* mid_w2  = (const float*)d_in[14];
    const float* mid_b2  = (const float*)d_in[15];
    float* out = (float*)d_out;

    __nv_bfloat16 *W1h, *W1l, *W2h, *W2l, *V1h, *V1l, *V2h, *V2l;
    float *Hf, *Hg, *G, *sf, *sg, *scf, *shf, *scg, *shg;
    cudaGetSymbolAddress((void**)&W1h, g_W1h); cudaGetSymbolAddress((void**)&W1l, g_W1l);
    cudaGetSymbolAddress((void**)&W2h, g_W2h); cudaGetSymbolAddress((void**)&W2l, g_W2l);
    cudaGetSymbolAddress((void**)&V1h, g_V1h); cudaGetSymbolAddress((void**)&V1l, g_V1l);
    cudaGetSymbolAddress((void**)&V2h, g_V2h); cudaGetSymbolAddress((void**)&V2l, g_V2l);
    cudaGetSymbolAddress((void**)&Hf,  g_Hf);  cudaGetSymbolAddress((void**)&Hg,  g_Hg);
    cudaGetSymbolAddress((void**)&G,   g_G);
    cudaGetSymbolAddress((void**)&sf,  g_sums_f);  cudaGetSymbolAddress((void**)&sg, g_sums_g);
    cudaGetSymbolAddress((void**)&scf, g_scale_f); cudaGetSymbolAddress((void**)&shf, g_shift_f);
    cudaGetSymbolAddress((void**)&scg, g_scale_g); cudaGetSymbolAddress((void**)&shg, g_shift_g);

    cudaFuncSetAttribute(mma_gemm_kernel<false>, cudaFuncAttributeMaxDynamicSharedMemorySize, GEMM_SMEM);
    cudaFuncSetAttribute(mma_gemm_kernel<true>,  cudaFuncAttributeMaxDynamicSharedMemorySize, GEMM_SMEM);

    auto blocks = [](int n4) { return (n4 + 255) / 256; };

    init_kernel<<<8, 256>>>();

    // weight splits (small, one-time per launch)
    { int n4 = D_L * D_L / 4; split_kernel<<<blocks(n4), 256>>>(mid_w1, W1h, W1l, n4); }
    { int n4 = D_L * D_L / 4; split_kernel<<<blocks(n4), 256>>>(mid_w2, W2h, W2l, n4); }
    { int n4 = D_G * D_L / 4; split_kernel<<<blocks(n4), 256>>>(vpt_w1, V1h, V1l, n4); }
    { int n4 = D_G * D_G / 4; split_kernel<<<blocks(n4), 256>>>(vpt_w2, V2h, V2l, n4); }

    // ----- fine path -----
    mma_gemm_kernel<false><<<dim3(D_L / 128, M_FINE / 128), 256, GEMM_SMEM>>>(
        fine_feat, W1h, W1l, mid_b1, nullptr, nullptr, Hf, D_L, D_L);

    stats_kernel<D_L, 256><<<M_FINE / 256, D_L>>>(Hf, M_FINE, sf);
    bn_finalize_kernel<D_L><<<1, D_L>>>(sf, mid_g1, mid_be1, 1.0f / (float)M_FINE, scf, shf);

    mma_gemm_kernel<true><<<dim3(D_L / 128, M_FINE / 128), 256, GEMM_SMEM>>>(
        Hf, W2h, W2l, mid_b2, scf, shf, out + OFF_FINE, D_L, D_L);

    token_mean_kernel<<<B_SZ, D_L>>>(out + OFF_FINE, out + OFF_TOP);
    topk_gather_kernel<<<B_SZ, 256>>>(fine_attn, out + OFF_FINE, out + OFF_TOP);

    // ----- global path -----
    mma_gemm_kernel<false><<<dim3(D_G / 128, B_SZ / 128), 256, GEMM_SMEM>>>(
        image_features, V1h, V1l, vpt_b1, nullptr, nullptr, Hg, D_G, D_L);

    stats_kernel<D_G, 64><<<B_SZ / 64, D_G>>>(Hg, B_SZ, sg);
    bn_finalize_kernel<D_G><<<1, D_G>>>(sg, vpt_g1, vpt_be1, 1.0f / (float)B_SZ, scg, shg);

    mma_gemm_kernel<true><<<dim3(D_G / 128, B_SZ / 128), 256, GEMM_SMEM>>>(
        Hg, V2h, V2l, vpt_b2, scg, shg, G, D_G, D_G);

    l2norm_kernel<<<B_SZ, 256>>>(G, logit_scale, out);
}

// round 10
// speedup vs baseline: 1.1716x; 1.1716x over previous
#include <cuda_runtime.h>
#include <cuda_bf16.h>
#include <cstdint>
#include <math.h>

// ---------------- problem constants ----------------
#define B_SZ     256
#define N_TOK    197
#define D_L      512
#define D_G      768
#define M_FINE   (B_SZ * N_TOK)          // 50432
#define TOPK     5

#define OFF_G    0
#define OFF_LS   (B_SZ * D_G)                         // 196608
#define OFF_FINE (OFF_LS + 1)                         // 196609
#define OFF_TOP  (OFF_FINE + (size_t)M_FINE * D_L)

// ---------------- device scratch ----------------
__device__ __align__(16) __nv_bfloat16 g_W1h[D_L * D_L], g_W1l[D_L * D_L];
__device__ __align__(16) __nv_bfloat16 g_W2h[D_L * D_L], g_W2l[D_L * D_L];
__device__ __align__(16) __nv_bfloat16 g_V1h[D_G * D_L], g_V1l[D_G * D_L];
__device__ __align__(16) __nv_bfloat16 g_V2h[D_G * D_G], g_V2l[D_G * D_G];
__device__ __align__(16) float g_Hf[(size_t)M_FINE * D_L];
__device__ __align__(16) float g_Hg[B_SZ * D_G];
__device__ __align__(16) float g_G [B_SZ * D_G];
__device__ __align__(16) float g_sums_f[2 * D_L];
__device__ __align__(16) float g_sums_g[2 * D_G];
__device__ __align__(16) float g_scale_f[D_L], g_shift_f[D_L];
__device__ __align__(16) float g_scale_g[D_G], g_shift_g[D_G];

// ---------------- helpers ----------------
__device__ __forceinline__ uint32_t s2u(const void* p) {
    uint32_t a;
    asm("{ .reg .u64 t; cvta.to.shared.u64 t, %1; cvt.u32.u64 %0, t; }" : "=r"(a) : "l"(p));
    return a;
}
__device__ __forceinline__ void ldsm_x4(uint32_t* r, uint32_t addr) {
    asm volatile("ldmatrix.sync.aligned.m8n8.x4.shared.b16 {%0,%1,%2,%3}, [%4];"
        : "=r"(r[0]), "=r"(r[1]), "=r"(r[2]), "=r"(r[3]) : "r"(addr));
}
__device__ __forceinline__ void mma16816(float* c, const uint32_t* a, const uint32_t* b) {
    asm volatile("mma.sync.aligned.m16n8k16.row.col.f32.bf16.bf16.f32 "
        "{%0,%1,%2,%3}, {%4,%5,%6,%7}, {%8,%9}, {%0,%1,%2,%3};"
        : "+f"(c[0]), "+f"(c[1]), "+f"(c[2]), "+f"(c[3])
        : "r"(a[0]), "r"(a[1]), "r"(a[2]), "r"(a[3]), "r"(b[0]), "r"(b[1]));
}
__device__ __forceinline__ void split1(float v, __nv_bfloat16& h, __nv_bfloat16& l) {
    h = __float2bfloat16(v);
    l = __float2bfloat16(v - __bfloat162float(h));
}

// ---------------- HMMA GEMM: C[M,N] = op(A)[M,K] @ W[N,K]^T + bias ----------------
// A fp32; split to bf16 hi/lo in-register at tile load. op(A)=relu(A*s+t) if BNRELU.
// W pre-split bf16 hi/lo. 3-term: ahi*bhi + ahi*blo + alo*bhi.
// CTA 128x128, BK=32, 8 warps, double-buffered smem.
// If STATS: per-column sum/sumsq of C accumulated into sums[0..N), sums[N..2N).
template<bool BNRELU, bool STATS>
__global__ void __launch_bounds__(256, 2)
mma_gemm_kernel(const float* __restrict__ A,
                const __nv_bfloat16* __restrict__ Wh, const __nv_bfloat16* __restrict__ Wl,
                const float* __restrict__ bias,
                const float* __restrict__ bnscale, const float* __restrict__ bnshift,
                float* __restrict__ C, float* __restrict__ sums, int N, int K)
{
    extern __shared__ char sm[];
    const uint32_t sbase = s2u(sm);
    const int tid  = threadIdx.x;
    const int lane = tid & 31, wid = tid >> 5;
    const int wm = wid & 3, wn = wid >> 2;          // 4 x 2 warp grid
    const int m0 = blockIdx.y * 128, n0 = blockIdx.x * 128;

    const int grp = lane >> 3, gr = lane & 7;

    const uint32_t aHiAddr = sbase + (uint32_t)((wm * 32 + gr + (grp & 1) * 8) * 80 + (grp >> 1) * 16);
    const uint32_t aLoAddr = aHiAddr + 10240u;
    const uint32_t bAddr   = sbase + (grp < 2 ? 20480u : 30720u)
                           + (uint32_t)((wn * 64 + gr) * 80 + (grp & 1) * 16);

    const int arow = tid >> 1;
    const int akk  = (tid & 1) * 16;
    const uint32_t aStsOff = (uint32_t)(arow * 80 + (tid & 1) * 32);

    float acc[2][8][4];
    #pragma unroll
    for (int i = 0; i < 2; i++)
        #pragma unroll
        for (int j = 0; j < 8; j++)
            #pragma unroll
            for (int q = 0; q < 4; q++) acc[i][j][q] = 0.0f;

    const int NT = K >> 5;
    float4 pa[4];

    auto ldgA = [&](int kc) {
        const float4* src = (const float4*)(A + (size_t)(m0 + arow) * K + kc + akk);
        #pragma unroll
        for (int i = 0; i < 4; i++) pa[i] = src[i];
    };
    auto cpB = [&](int kc, int stage) {
        const uint32_t so = (uint32_t)stage * 40960u;
        #pragma unroll
        for (int p = 0; p < 2; p++) {
            int i = tid + 256 * p; int row = i >> 2, sg = i & 3;
            uint32_t dh = sbase + so + 20480u + (uint32_t)(row * 80 + sg * 16);
            uint32_t dl = dh + 10240u;
            const __nv_bfloat16* sh = Wh + (size_t)(n0 + row) * K + kc + sg * 8;
            const __nv_bfloat16* sl = Wl + (size_t)(n0 + row) * K + kc + sg * 8;
            asm volatile("cp.async.cg.shared.global [%0], [%1], 16;" :: "r"(dh), "l"(sh));
            asm volatile("cp.async.cg.shared.global [%0], [%1], 16;" :: "r"(dl), "l"(sl));
        }
        asm volatile("cp.async.commit_group;" ::: "memory");
    };

    ldgA(0);
    cpB(0, 0);

    for (int kt = 0; kt < NT; kt++) {
        const int stage = kt & 1;
        const uint32_t so = (uint32_t)stage * 40960u;
        const int kc = kt << 5;

        __syncthreads();

        // ---- BN + hi/lo split + STS A(kt) ----
        {
            __nv_bfloat162 hp[8], lp[8];
            #pragma unroll
            for (int i = 0; i < 4; i++) {
                float4 v = pa[i];
                if (BNRELU) {
                    float4 s = ((const float4*)(bnscale + kc + akk))[i];
                    float4 t = ((const float4*)(bnshift + kc + akk))[i];
                    v.x = fmaxf(fmaf(v.x, s.x, t.x), 0.0f);
                    v.y = fmaxf(fmaf(v.y, s.y, t.y), 0.0f);
                    v.z = fmaxf(fmaf(v.z, s.z, t.z), 0.0f);
                    v.w = fmaxf(fmaf(v.w, s.w, t.w), 0.0f);
                }
                __nv_bfloat16 h0, h1, h2, h3, l0, l1, l2, l3;
                split1(v.x, h0, l0); split1(v.y, h1, l1);
                split1(v.z, h2, l2); split1(v.w, h3, l3);
                hp[2 * i]     = __halves2bfloat162(h0, h1);
                hp[2 * i + 1] = __halves2bfloat162(h2, h3);
                lp[2 * i]     = __halves2bfloat162(l0, l1);
                lp[2 * i + 1] = __halves2bfloat162(l2, l3);
            }
            char* dsth = sm + so + aStsOff;
            char* dstl = dsth + 10240;
            ((uint4*)dsth)[0] = ((uint4*)hp)[0];
            ((uint4*)dsth)[1] = ((uint4*)hp)[1];
            ((uint4*)dstl)[0] = ((uint4*)lp)[0];
            ((uint4*)dstl)[1] = ((uint4*)lp)[1];
        }

        if (kt + 1 < NT) {
            ldgA(kc + 32);
            cpB(kc + 32, stage ^ 1);
            asm volatile("cp.async.wait_group 1;" ::: "memory");
        } else {
            asm volatile("cp.async.wait_group 0;" ::: "memory");
        }
        __syncthreads();

        #pragma unroll
        for (int k16 = 0; k16 < 2; k16++) {
            const uint32_t kb = so + (uint32_t)(k16 * 32);
            uint32_t aHi[2][4], aLo[2][4];
            #pragma unroll
            for (int mt = 0; mt < 2; mt++) {
                ldsm_x4(aHi[mt], aHiAddr + kb + (uint32_t)(mt * 1280));
                ldsm_x4(aLo[mt], aLoAddr + kb + (uint32_t)(mt * 1280));
            }
            #pragma unroll
            for (int nt = 0; nt < 8; nt++) {
                uint32_t bb[4];
                ldsm_x4(bb, bAddr + kb + (uint32_t)(nt * 640));
                mma16816(acc[0][nt], aHi[0], bb + 0);
                mma16816(acc[1][nt], aHi[1], bb + 0);
                mma16816(acc[0][nt], aHi[0], bb + 2);
                mma16816(acc[1][nt], aHi[1], bb + 2);
                mma16816(acc[0][nt], aLo[0], bb + 0);
                mma16816(acc[1][nt], aLo[1], bb + 0);
            }
        }
    }

    // ---- epilogue: +bias, stores, optional fused column stats ----
    float* ssum = (float*)sm;   // [0..127]=col sum, [128..255]=col sumsq
    if (STATS) {
        __syncthreads();
        if (tid < 256) ssum[tid] = 0.0f;
        __syncthreads();
    }

    const int erow = m0 + wm * 32 + (lane >> 2);
    const int ecol = n0 + wn * 64 + ((lane & 3) << 1);
    #pragma unroll
    for (int nt = 0; nt < 8; nt++) {
        int c = ecol + nt * 8;
        float b0 = __ldg(&bias[c]), b1 = __ldg(&bias[c + 1]);
        float cs0 = 0.f, cq0 = 0.f, cs1 = 0.f, cq1 = 0.f;
        #pragma unroll
        for (int mt = 0; mt < 2; mt++) {
            int r = erow + mt * 16;
            float v0 = acc[mt][nt][0] + b0;
            float v1 = acc[mt][nt][1] + b1;
            float v2 = acc[mt][nt][2] + b0;
            float v3 = acc[mt][nt][3] + b1;
            C[(size_t)r * N + c]           = v0;
            C[(size_t)r * N + c + 1]       = v1;
            C[(size_t)(r + 8) * N + c]     = v2;
            C[(size_t)(r + 8) * N + c + 1] = v3;
            if (STATS) {
                cs0 += v0 + v2; cq0 = fmaf(v0, v0, fmaf(v2, v2, cq0));
                cs1 += v1 + v3; cq1 = fmaf(v1, v1, fmaf(v3, v3, cq1));
            }
        }
        if (STATS) {
            // lanes l, l^4, l^8, l^16 hold the same columns (different rows)
            #pragma unroll
            for (int o = 4; o <= 16; o <<= 1) {
                cs0 += __shfl_xor_sync(0xffffffffu, cs0, o);
                cq0 += __shfl_xor_sync(0xffffffffu, cq0, o);
                cs1 += __shfl_xor_sync(0xffffffffu, cs1, o);
                cq1 += __shfl_xor_sync(0xffffffffu, cq1, o);
            }
            if (lane < 4) {
                int lc = wn * 64 + lane * 2 + nt * 8;
                atomicAdd(&ssum[lc],           cs0);
                atomicAdd(&ssum[128 + lc],     cq0);
                atomicAdd(&ssum[lc + 1],       cs1);
                atomicAdd(&ssum[128 + lc + 1], cq1);
            }
        }
    }
    if (STATS) {
        __syncthreads();
        if (tid < 128) {
            atomicAdd(&sums[n0 + tid],     ssum[tid]);
            atomicAdd(&sums[N + n0 + tid], ssum[128 + tid]);
        }
    }
}

#define GEMM_SMEM 81920

// ---------------- weight split fp32 -> bf16 hi/lo ----------------
__global__ void split_kernel(const float* __restrict__ x,
                             __nv_bfloat16* __restrict__ hi,
                             __nv_bfloat16* __restrict__ lo, int n4) {
    int i = blockIdx.x * blockDim.x + threadIdx.x;
    if (i >= n4) return;
    float4 v = ((const float4*)x)[i];
    __nv_bfloat16 h0, h1, h2, h3, l0, l1, l2, l3;
    split1(v.x, h0, l0); split1(v.y, h1, l1); split1(v.z, h2, l2); split1(v.w, h3, l3);
    ((__nv_bfloat162*)hi)[2 * (size_t)i]     = __halves2bfloat162(h0, h1);
    ((__nv_bfloat162*)hi)[2 * (size_t)i + 1] = __halves2bfloat162(h2, h3);
    ((__nv_bfloat162*)lo)[2 * (size_t)i]     = __halves2bfloat162(l0, l1);
    ((__nv_bfloat162*)lo)[2 * (size_t)i + 1] = __halves2bfloat162(l2, l3);
}

// ---------------- init: zero BN accumulators ----------------
__global__ void init_kernel() {
    int t = blockIdx.x * blockDim.x + threadIdx.x;
    if (t < 2 * D_L) g_sums_f[t] = 0.0f;
    if (t < 2 * D_G) g_sums_g[t] = 0.0f;
}

template<int C>
__global__ void bn_finalize_kernel(const float* __restrict__ sums,
                                   const float* __restrict__ gamma,
                                   const float* __restrict__ beta,
                                   float invM,
                                   float* __restrict__ scale,
                                   float* __restrict__ shift) {
    int c = threadIdx.x;
    if (c >= C) return;
    float m   = sums[c] * invM;
    float var = sums[C + c] * invM - m * m;
    float inv = rsqrtf(var + 1e-5f);
    float sc  = gamma[c] * inv;
    scale[c] = sc;
    shift[c] = beta[c] - m * sc;
}

// ---------------- L2 normalize + logit_scale ----------------
__global__ void l2norm_kernel(const float* __restrict__ G,
                              const float* __restrict__ ls,
                              float* __restrict__ out) {
    __shared__ float red[256];
    const int r = blockIdx.x, t = threadIdx.x;
    const float* g = G + (size_t)r * D_G;
    float s = 0.0f;
    for (int c = t; c < D_G; c += 256) { float v = g[c]; s = fmaf(v, v, s); }
    red[t] = s; __syncthreads();
    for (int o = 128; o > 0; o >>= 1) {
        if (t < o) red[t] += red[t + o];
        __syncthreads();
    }
    float inv = rsqrtf(red[0]);
    for (int c = t; c < D_G; c += 256)
        out[OFF_G + (size_t)r * D_G + c] = g[c] * inv;
    if (r == 0 && t == 0) out[OFF_LS] = expf(ls[0]);
}

// ---------------- token mean -> top row 6 ----------------
__global__ void token_mean_kernel(const float* __restrict__ X2, float* __restrict__ outTop) {
    const int b = blockIdx.x, d = threadIdx.x;   // blockDim = 512
    const float* p = X2 + (size_t)b * N_TOK * D_L + d;
    float s = 0.0f;
    #pragma unroll 4
    for (int n = 0; n < N_TOK; n++) s += p[(size_t)n * D_L];
    outTop[((size_t)b * (TOPK + 2) + (TOPK + 1)) * D_L + d] = s * (1.0f / (float)N_TOK);
}

// ---------------- top-k gather ----------------
__global__ void topk_gather_kernel(const float* __restrict__ attn,
                                   const float* __restrict__ X2,
                                   float* __restrict__ outTop) {
    __shared__ float sv[256];
    __shared__ int   si[256];
    __shared__ int   sel[TOPK + 1];
    const int b = blockIdx.x, t = threadIdx.x;
    const float NEG = __int_as_float(0xff800000);

    float myv = (t < N_TOK - 1) ? attn[(size_t)b * (N_TOK - 1) + t] : NEG;
    if (t == 0) sel[0] = 0;
    __syncthreads();

    for (int k = 0; k < TOPK; k++) {
        sv[t] = myv; si[t] = t;
        __syncthreads();
        for (int o = 128; o > 0; o >>= 1) {
            if (t < o) {
                float v2 = sv[t + o]; int i2 = si[t + o];
                if (v2 > sv[t] || (v2 == sv[t] && i2 < si[t])) { sv[t] = v2; si[t] = i2; }
            }
            __syncthreads();
        }
        int win = si[0];
        if (t == 0)  sel[k + 1] = win + 1;
        if (t == win) myv = NEG;
        __syncthreads();
    }

    #pragma unroll
    for (int j = 0; j < TOPK + 1; j++) {
        int row = sel[j];
        const float* src = X2 + ((size_t)b * N_TOK + row) * D_L;
        float* dst = outTop + ((size_t)b * (TOPK + 2) + j) * D_L;
        for (int d = t; d < D_L; d += 256) dst[d] = src[d];
    }
}

// ---------------- launch ----------------
extern "C" void kernel_launch(void* const* d_in, const int* in_sizes, int n_in,
                              void* d_out, int out_size)
{
    const float* image_features = (const float*)d_in[0];
    const float* fine_feat      = (const float*)d_in[1];
    const float* fine_attn      = (const float*)d_in[2];
    const float* logit_scale    = (const float*)d_in[3];
    const float* vpt_w1  = (const float*)d_in[4];
    const float* vpt_b1  = (const float*)d_in[5];
    const float* vpt_g1  = (const float*)d_in[6];
    const float* vpt_be1 = (const float*)d_in[7];
    const float* vpt_w2  = (const float*)d_in[8];
    const float* vpt_b2  = (const float*)d_in[9];
    const float* mid_w1  = (const float*)d_in[10];
    const float* mid_b1  = (const float*)d_in[11];
    const float* mid_g1  = (const float*)d_in[12];
    const float* mid_be1 = (const float*)d_in[13];
    const float* mid_w2  = (const float*)d_in[14];
    const float* mid_b2  = (const float*)d_in[15];
    float* out = (float*)d_out;

    __nv_bfloat16 *W1h, *W1l, *W2h, *W2l, *V1h, *V1l, *V2h, *V2l;
    float *Hf, *Hg, *G, *sf, *sg, *scf, *shf, *scg, *shg;
    cudaGetSymbolAddress((void**)&W1h, g_W1h); cudaGetSymbolAddress((void**)&W1l, g_W1l);
    cudaGetSymbolAddress((void**)&W2h, g_W2h); cudaGetSymbolAddress((void**)&W2l, g_W2l);
    cudaGetSymbolAddress((void**)&V1h, g_V1h); cudaGetSymbolAddress((void**)&V1l, g_V1l);
    cudaGetSymbolAddress((void**)&V2h, g_V2h); cudaGetSymbolAddress((void**)&V2l, g_V2l);
    cudaGetSymbolAddress((void**)&Hf,  g_Hf);  cudaGetSymbolAddress((void**)&Hg,  g_Hg);
    cudaGetSymbolAddress((void**)&G,   g_G);
    cudaGetSymbolAddress((void**)&sf,  g_sums_f);  cudaGetSymbolAddress((void**)&sg, g_sums_g);
    cudaGetSymbolAddress((void**)&scf, g_scale_f); cudaGetSymbolAddress((void**)&shf, g_shift_f);
    cudaGetSymbolAddress((void**)&scg, g_scale_g); cudaGetSymbolAddress((void**)&shg, g_shift_g);

    cudaFuncSetAttribute(mma_gemm_kernel<false, true>,  cudaFuncAttributeMaxDynamicSharedMemorySize, GEMM_SMEM);
    cudaFuncSetAttribute(mma_gemm_kernel<true,  false>, cudaFuncAttributeMaxDynamicSharedMemorySize, GEMM_SMEM);

    // fork/join resources (host-side, created once on the uncaptured correctness call)
    static cudaStream_t s1 = nullptr;
    static cudaEvent_t evFork = nullptr, evJoin = nullptr;
    if (s1 == nullptr) {
        cudaStreamCreateWithFlags(&s1, cudaStreamNonBlocking);
        cudaEventCreateWithFlags(&evFork, cudaEventDisableTiming);
        cudaEventCreateWithFlags(&evJoin, cudaEventDisableTiming);
    }

    auto blocks = [](int n4) { return (n4 + 255) / 256; };

    // 0) zero BN accumulators, then fork the global path
    init_kernel<<<8, 256>>>();
    cudaEventRecord(evFork, 0);
    cudaStreamWaitEvent(s1, evFork, 0);

    // ----- global path (stream s1) -----
    { int n4 = D_G * D_L / 4; split_kernel<<<blocks(n4), 256, 0, s1>>>(vpt_w1, V1h, V1l, n4); }
    { int n4 = D_G * D_G / 4; split_kernel<<<blocks(n4), 256, 0, s1>>>(vpt_w2, V2h, V2l, n4); }

    mma_gemm_kernel<false, true><<<dim3(D_G / 128, B_SZ / 128), 256, GEMM_SMEM, s1>>>(
        image_features, V1h, V1l, vpt_b1, nullptr, nullptr, Hg, sg, D_G, D_L);
    bn_finalize_kernel<D_G><<<1, D_G, 0, s1>>>(sg, vpt_g1, vpt_be1, 1.0f / (float)B_SZ, scg, shg);
    mma_gemm_kernel<true, false><<<dim3(D_G / 128, B_SZ / 128), 256, GEMM_SMEM, s1>>>(
        Hg, V2h, V2l, vpt_b2, scg, shg, G, nullptr, D_G, D_G);
    l2norm_kernel<<<B_SZ, 256, 0, s1>>>(G, logit_scale, out);
    cudaEventRecord(evJoin, s1);

    // ----- fine path (default stream) -----
    { int n4 = D_L * D_L / 4; split_kernel<<<blocks(n4), 256>>>(mid_w1, W1h, W1l, n4); }
    { int n4 = D_L * D_L / 4; split_kernel<<<blocks(n4), 256>>>(mid_w2, W2h, W2l, n4); }

    mma_gemm_kernel<false, true><<<dim3(D_L / 128, M_FINE / 128), 256, GEMM_SMEM>>>(
        fine_feat, W1h, W1l, mid_b1, nullptr, nullptr, Hf, sf, D_L, D_L);
    bn_finalize_kernel<D_L><<<1, D_L>>>(sf, mid_g1, mid_be1, 1.0f / (float)M_FINE, scf, shf);
    mma_gemm_kernel<true, false><<<dim3(D_L / 128, M_FINE / 128), 256, GEMM_SMEM>>>(
        Hf, W2h, W2l, mid_b2, scf, shf, out + OFF_FINE, nullptr, D_L, D_L);

    token_mean_kernel<<<B_SZ, D_L>>>(out + OFF_FINE, out + OFF_TOP);
    topk_gather_kernel<<<B_SZ, 256>>>(fine_attn, out + OFF_FINE, out + OFF_TOP);

    // join
    cudaStreamWaitEvent(0, evJoin, 0);
}